// round 6
// baseline (speedup 1.0000x reference)
#include <cuda_runtime.h>
#include <cuda_fp16.h>
#include <cstdint>

// ---------------------------------------------------------------------------
// Problem constants
// ---------------------------------------------------------------------------
#define IN_F   4096
#define OUT_F  4096
#define BLOCK_ 16
#define D_LAT  16
#define HID    64
#define KSIZE  65536
#define NB     (IN_F * OUT_F / BLOCK_)
#define M_ROWS 8192
#define K_DIM  4096
#define N_DIM  4096

// GEMM tiling: CTA 128x128, 4 warps of 64x64, BK=64, 3 stages
#define BM 128
#define BN 128
#define BK 64
#define STAGES 3
#define NK (K_DIM / BK)   // 64
#define THREADS 128

// ---------------------------------------------------------------------------
// Scratch
// ---------------------------------------------------------------------------
__device__ float  g_table[(size_t)KSIZE * BLOCK_];
__device__ __half g_Wh[(size_t)OUT_F * IN_F];
__device__ __half g_xh[(size_t)M_ROWS * IN_F];

// ---------------------------------------------------------------------------
// Helpers
// ---------------------------------------------------------------------------
__device__ __forceinline__ uint32_t smem_u32(const void* p) {
    return (uint32_t)__cvta_generic_to_shared(p);
}
#define SWZ(o) ((o) ^ (((o) >> 3) & 0x70))

__device__ __forceinline__ void cp16(uint32_t saddr, const void* gaddr) {
    asm volatile("cp.async.cg.shared.global [%0], [%1], 16;" :: "r"(saddr), "l"(gaddr));
}
#define CP_COMMIT() asm volatile("cp.async.commit_group;" ::: "memory")
#define CP_WAIT0()  asm volatile("cp.async.wait_group 0;" ::: "memory")
#define CP_WAIT1()  asm volatile("cp.async.wait_group 1;" ::: "memory")

__device__ __forceinline__ void ldm_x4(uint32_t addr, uint32_t& r0, uint32_t& r1,
                                       uint32_t& r2, uint32_t& r3) {
    asm volatile("ldmatrix.sync.aligned.m8n8.x4.shared.b16 {%0,%1,%2,%3}, [%4];"
                 : "=r"(r0), "=r"(r1), "=r"(r2), "=r"(r3) : "r"(addr));
}

__device__ __forceinline__ void mma16816(float& c0, float& c1, float& c2, float& c3,
                                         uint32_t a0, uint32_t a1, uint32_t a2, uint32_t a3,
                                         uint32_t b0, uint32_t b1) {
    asm volatile("mma.sync.aligned.m16n8k16.row.col.f32.f16.f16.f32 "
                 "{%0,%1,%2,%3}, {%4,%5,%6,%7}, {%8,%9}, {%0,%1,%2,%3};"
                 : "+f"(c0), "+f"(c1), "+f"(c2), "+f"(c3)
                 : "r"(a0), "r"(a1), "r"(a2), "r"(a3), "r"(b0), "r"(b1));
}

// ---------------------------------------------------------------------------
// Kernel 1: decode every codebook entry once (65536 x 16)
// ---------------------------------------------------------------------------
__global__ void __launch_bounds__(256)
precompute_table(const float* __restrict__ codebook,
                 const float* __restrict__ W1, const float* __restrict__ b1,
                 const float* __restrict__ W2, const float* __restrict__ b2)
{
    __shared__ float sW1[D_LAT * HID];
    __shared__ float sW2[HID * BLOCK_];
    __shared__ float sb1[HID];
    __shared__ float sb2[BLOCK_];

    const int tid = threadIdx.x;
    for (int i = tid; i < D_LAT * HID; i += 256) sW1[i] = W1[i];
    for (int i = tid; i < HID * BLOCK_; i += 256) sW2[i] = W2[i];
    if (tid < HID)    sb1[tid] = b1[tid];
    if (tid < BLOCK_) sb2[tid] = b2[tid];
    __syncthreads();

    const int e = blockIdx.x * 256 + tid;

    float c[D_LAT];
    const float4* cb = reinterpret_cast<const float4*>(codebook + (size_t)e * D_LAT);
    {
        float4 v0 = cb[0], v1 = cb[1], v2 = cb[2], v3 = cb[3];
        c[0]=v0.x; c[1]=v0.y; c[2]=v0.z; c[3]=v0.w;
        c[4]=v1.x; c[5]=v1.y; c[6]=v1.z; c[7]=v1.w;
        c[8]=v2.x; c[9]=v2.y; c[10]=v2.z; c[11]=v2.w;
        c[12]=v3.x; c[13]=v3.y; c[14]=v3.z; c[15]=v3.w;
    }

    float h[HID];
    #pragma unroll
    for (int j = 0; j < HID; ++j) h[j] = sb1[j];
    #pragma unroll
    for (int d = 0; d < D_LAT; ++d) {
        const float cd = c[d];
        #pragma unroll
        for (int j = 0; j < HID; ++j) h[j] = fmaf(cd, sW1[d * HID + j], h[j]);
    }
    #pragma unroll
    for (int j = 0; j < HID; ++j) h[j] = fmaxf(h[j], 0.0f);

    float blk[BLOCK_];
    #pragma unroll
    for (int k = 0; k < BLOCK_; ++k) blk[k] = sb2[k];
    #pragma unroll
    for (int j = 0; j < HID; ++j) {
        const float hj = h[j];
        #pragma unroll
        for (int k = 0; k < BLOCK_; ++k) blk[k] = fmaf(hj, sW2[j * BLOCK_ + k], blk[k]);
    }

    float4* dst = reinterpret_cast<float4*>(g_table + (size_t)e * BLOCK_);
    dst[0] = make_float4(blk[0], blk[1], blk[2], blk[3]);
    dst[1] = make_float4(blk[4], blk[5], blk[6], blk[7]);
    dst[2] = make_float4(blk[8], blk[9], blk[10], blk[11]);
    dst[3] = make_float4(blk[12], blk[13], blk[14], blk[15]);
}

// ---------------------------------------------------------------------------
// Kernel 2: gather + de-standardize + fp16 convert into g_Wh
// ---------------------------------------------------------------------------
__global__ void __launch_bounds__(256)
gather_kernel(const int* __restrict__ idx,
              const float* __restrict__ scale, const float* __restrict__ shift)
{
    __shared__ float s_s, s_sh;
    const int o = blockIdx.x;
    if (threadIdx.x == 0) { s_s = scale[o]; s_sh = shift[o]; }
    __syncthreads();

    const int b = o * 256 + threadIdx.x;
    const int e = idx[b];
    const float s  = s_s;
    const float sh = s_sh;

    const float4* src = reinterpret_cast<const float4*>(g_table + (size_t)e * BLOCK_);
    float4 v0 = src[0], v1 = src[1], v2 = src[2], v3 = src[3];
    float blk[16] = {v0.x,v0.y,v0.z,v0.w, v1.x,v1.y,v1.z,v1.w,
                     v2.x,v2.y,v2.z,v2.w, v3.x,v3.y,v3.z,v3.w};

    __align__(16) __half h16[16];
    #pragma unroll
    for (int q = 0; q < 16; ++q) h16[q] = __float2half_rn(fmaf(blk[q], s, sh));

    const size_t base = (size_t)o * IN_F + (size_t)threadIdx.x * 16;
    reinterpret_cast<uint4*>(g_Wh + base)[0] = reinterpret_cast<uint4*>(h16)[0];
    reinterpret_cast<uint4*>(g_Wh + base)[1] = reinterpret_cast<uint4*>(h16)[1];
}

// ---------------------------------------------------------------------------
// Kernel 3: convert x -> fp16
// ---------------------------------------------------------------------------
__global__ void __launch_bounds__(256)
convert_x_kernel(const float* __restrict__ x)
{
    const size_t t = (size_t)blockIdx.x * 256 + threadIdx.x;
    const size_t base = t * 8;
    float4 a = *reinterpret_cast<const float4*>(x + base);
    float4 b = *reinterpret_cast<const float4*>(x + base + 4);
    __align__(16) __half h[8];
    h[0]=__float2half_rn(a.x); h[1]=__float2half_rn(a.y);
    h[2]=__float2half_rn(a.z); h[3]=__float2half_rn(a.w);
    h[4]=__float2half_rn(b.x); h[5]=__float2half_rn(b.y);
    h[6]=__float2half_rn(b.z); h[7]=__float2half_rn(b.w);
    *reinterpret_cast<uint4*>(g_xh + base) = *reinterpret_cast<uint4*>(h);
}

// ---------------------------------------------------------------------------
// Kernel 4: fp16 mma.sync GEMM, 4 warps of 64x64.
// Cross-iteration fragment pipelining: kk=0 frags of stage it+1 are loaded
// during kk=3 of stage it (legal because wait_group 0 guarantees residency).
// ---------------------------------------------------------------------------
#define STG_BYTES 32768
#define SMEM_TOTAL (STAGES * STG_BYTES)   // 96 KB; 2 CTAs/SM

__device__ __forceinline__ void load_stage(uint32_t sbase, int buf, int it,
                                           int bm0, int bn0, int tid)
{
    const uint32_t sA = sbase + buf * STG_BYTES;
    const uint32_t sB = sA + 16384;
    const size_t k0 = (size_t)it * BK;
    #pragma unroll
    for (int i = 0; i < 8; ++i) {
        const int c = tid + i * 128;          // 0..1023
        const int row = c >> 3;
        const int cx  = c & 7;
        const uint32_t soff = SWZ((uint32_t)(row * 128 + cx * 16));
        cp16(sA + soff, g_xh + (size_t)(bm0 + row) * K_DIM + k0 + cx * 8);
        cp16(sB + soff, g_Wh + (size_t)(bn0 + row) * K_DIM + k0 + cx * 8);
    }
}

__global__ void __launch_bounds__(THREADS, 2)
gemm_kernel(const float* __restrict__ bias, float* __restrict__ C)
{
    extern __shared__ char smem[];
    const uint32_t sbase = smem_u32(smem);
    const int tid  = threadIdx.x;
    const int lane = tid & 31;
    const int w    = tid >> 5;          // 0..3
    const int wm   = w >> 1;
    const int wn   = w & 1;
    const int bm0  = blockIdx.y * BM;
    const int bn0  = blockIdx.x * BN;

    float acc[4][8][4];
    #pragma unroll
    for (int mt = 0; mt < 4; ++mt)
        #pragma unroll
        for (int nt = 0; nt < 8; ++nt)
            #pragma unroll
            for (int q = 0; q < 4; ++q) acc[mt][nt][q] = 0.0f;

    // Prologue: fill buffers 0 and 1
    load_stage(sbase, 0, 0, bm0, bn0, tid);
    CP_COMMIT();
    load_stage(sbase, 1, 1, bm0, bn0, tid);
    CP_COMMIT();

    // Per-lane ldmatrix base offsets
    const int a_row = wm * 64 + (lane & 15);
    const int a_cb  = ((lane >> 4) & 1) * 16;
    const int b_row = wn * 64 + ((lane >> 4) & 1) * 8 + (lane & 7);
    const int b_cb  = ((lane >> 3) & 1) * 16;

    uint32_t a[2][4][4];
    uint32_t b[2][8][2];

    // Wait for stage 0, preload its kk=0 fragments into frag buffer 0.
    CP_WAIT1();
    __syncthreads();
    {
        const uint32_t sA = sbase;
        const uint32_t sB = sA + 16384;
        #pragma unroll
        for (int mt = 0; mt < 4; ++mt) {
            const uint32_t off = (uint32_t)((a_row + mt * 16) * 128 + a_cb);
            ldm_x4(sA + SWZ(off), a[0][mt][0], a[0][mt][1], a[0][mt][2], a[0][mt][3]);
        }
        #pragma unroll
        for (int ntp = 0; ntp < 4; ++ntp) {
            const uint32_t off = (uint32_t)((b_row + ntp * 16) * 128 + b_cb);
            uint32_t r0, r1, r2, r3;
            ldm_x4(sB + SWZ(off), r0, r1, r2, r3);
            b[0][ntp*2+0][0] = r0; b[0][ntp*2+0][1] = r1;
            b[0][ntp*2+1][0] = r2; b[0][ntp*2+1][1] = r3;
        }
    }

    for (int it = 0; it < NK; ++it) {
        // Stage it AND it+1 both resident after this (groups <= it+1 complete).
        CP_WAIT0();
        __syncthreads();   // protects buffer (it+2)%3 (read in iter it-1) before rewrite

        const int nxt = it + 2;
        if (nxt < NK) load_stage(sbase, nxt % STAGES, nxt, bm0, bn0, tid);
        CP_COMMIT();

        const uint32_t sA = sbase + (it % STAGES) * STG_BYTES;
        const uint32_t sB = sA + 16384;
        // Next stage buffer (resident; not written until iter it+2's loads)
        const uint32_t sAn = sbase + ((it + 1) % STAGES) * STG_BYTES;
        const uint32_t sBn = sAn + 16384;
        const bool have_next = (it + 1) < NK;

        #pragma unroll
        for (int kk = 0; kk < 4; ++kk) {
            const int cur = kk & 1;
            const int nxb = cur ^ 1;
            if (kk < 3) {
                const int kc = (kk + 1) * 32;
                #pragma unroll
                for (int mt = 0; mt < 4; ++mt) {
                    const uint32_t off = (uint32_t)((a_row + mt * 16) * 128 + kc + a_cb);
                    ldm_x4(sA + SWZ(off), a[nxb][mt][0], a[nxb][mt][1], a[nxb][mt][2], a[nxb][mt][3]);
                }
                #pragma unroll
                for (int ntp = 0; ntp < 4; ++ntp) {
                    const uint32_t off = (uint32_t)((b_row + ntp * 16) * 128 + kc + b_cb);
                    uint32_t r0, r1, r2, r3;
                    ldm_x4(sB + SWZ(off), r0, r1, r2, r3);
                    b[nxb][ntp*2+0][0] = r0; b[nxb][ntp*2+0][1] = r1;
                    b[nxb][ntp*2+1][0] = r2; b[nxb][ntp*2+1][1] = r3;
                }
            } else if (have_next) {
                // Preload kk=0 fragments of the NEXT stage (cross-iteration pipe)
                #pragma unroll
                for (int mt = 0; mt < 4; ++mt) {
                    const uint32_t off = (uint32_t)((a_row + mt * 16) * 128 + a_cb);
                    ldm_x4(sAn + SWZ(off), a[nxb][mt][0], a[nxb][mt][1], a[nxb][mt][2], a[nxb][mt][3]);
                }
                #pragma unroll
                for (int ntp = 0; ntp < 4; ++ntp) {
                    const uint32_t off = (uint32_t)((b_row + ntp * 16) * 128 + b_cb);
                    uint32_t r0, r1, r2, r3;
                    ldm_x4(sBn + SWZ(off), r0, r1, r2, r3);
                    b[nxb][ntp*2+0][0] = r0; b[nxb][ntp*2+0][1] = r1;
                    b[nxb][ntp*2+1][0] = r2; b[nxb][ntp*2+1][1] = r3;
                }
            }
            #pragma unroll
            for (int mt = 0; mt < 4; ++mt)
                #pragma unroll
                for (int nt = 0; nt < 8; ++nt)
                    mma16816(acc[mt][nt][0], acc[mt][nt][1], acc[mt][nt][2], acc[mt][nt][3],
                             a[cur][mt][0], a[cur][mt][1], a[cur][mt][2], a[cur][mt][3],
                             b[cur][nt][0], b[cur][nt][1]);
        }
    }

    // Epilogue
    #pragma unroll
    for (int nt = 0; nt < 8; ++nt) {
        const int col = bn0 + wn * 64 + nt * 8 + (lane & 3) * 2;
        const float bx = __ldg(bias + col);
        const float by = __ldg(bias + col + 1);
        #pragma unroll
        for (int mt = 0; mt < 4; ++mt) {
            const int r0 = bm0 + wm * 64 + mt * 16 + (lane >> 2);
            float2 v0 = make_float2(acc[mt][nt][0] + bx, acc[mt][nt][1] + by);
            float2 v1 = make_float2(acc[mt][nt][2] + bx, acc[mt][nt][3] + by);
            *reinterpret_cast<float2*>(C + (size_t)r0 * N_DIM + col) = v0;
            *reinterpret_cast<float2*>(C + (size_t)(r0 + 8) * N_DIM + col) = v1;
        }
    }
}

// ---------------------------------------------------------------------------
// kernel_launch
// ---------------------------------------------------------------------------
extern "C" void kernel_launch(void* const* d_in, const int* in_sizes, int n_in,
                              void* d_out, int out_size)
{
    const float* x        = (const float*)d_in[0];
    const int*   y_in_idx = (const int*)  d_in[1];
    const float* codebook = (const float*)d_in[2];
    const float* W1       = (const float*)d_in[3];
    const float* b1       = (const float*)d_in[4];
    const float* W2       = (const float*)d_in[5];
    const float* b2       = (const float*)d_in[6];
    const float* scale    = (const float*)d_in[7];
    const float* shift    = (const float*)d_in[8];
    const float* bias     = (const float*)d_in[9];
    float* out = (float*)d_out;

    cudaFuncSetAttribute(gemm_kernel, cudaFuncAttributeMaxDynamicSharedMemorySize, SMEM_TOTAL);

    precompute_table<<<KSIZE / 256, 256>>>(codebook, W1, b1, W2, b2);
    gather_kernel<<<OUT_F, 256>>>(y_in_idx, scale, shift);
    convert_x_kernel<<<(size_t)M_ROWS * K_DIM / (256 * 8), 256>>>(x);

    dim3 grid(N_DIM / BN, M_ROWS / BM);
    gemm_kernel<<<grid, THREADS, SMEM_TOTAL>>>(bias, out);
}

// round 7
// speedup vs baseline: 1.0098x; 1.0098x over previous
#include <cuda_runtime.h>
#include <cuda_fp16.h>
#include <cstdint>

// ---------------------------------------------------------------------------
// Problem constants
// ---------------------------------------------------------------------------
#define IN_F   4096
#define OUT_F  4096
#define BLOCK_ 16
#define D_LAT  16
#define HID    64
#define KSIZE  65536
#define NB     (IN_F * OUT_F / BLOCK_)
#define M_ROWS 8192
#define K_DIM  4096
#define N_DIM  4096

// GEMM tiling: CTA 128x128, 4 warps of 64x64, BK=64, 3 stages
#define BM 128
#define BN 128
#define BK 64
#define STAGES 3
#define NK (K_DIM / BK)   // 64
#define THREADS 128

// ---------------------------------------------------------------------------
// Scratch
// ---------------------------------------------------------------------------
__device__ float  g_table[(size_t)KSIZE * BLOCK_];
__device__ __half g_Wh[(size_t)OUT_F * IN_F];
__device__ __half g_xh[(size_t)M_ROWS * IN_F];

// ---------------------------------------------------------------------------
// Helpers
// ---------------------------------------------------------------------------
__device__ __forceinline__ uint32_t smem_u32(const void* p) {
    return (uint32_t)__cvta_generic_to_shared(p);
}
#define SWZ(o) ((o) ^ (((o) >> 3) & 0x70))

__device__ __forceinline__ void cp16(uint32_t saddr, const void* gaddr) {
    asm volatile("cp.async.cg.shared.global [%0], [%1], 16;" :: "r"(saddr), "l"(gaddr));
}
#define CP_COMMIT() asm volatile("cp.async.commit_group;" ::: "memory")
#define CP_WAIT1()  asm volatile("cp.async.wait_group 1;" ::: "memory")

__device__ __forceinline__ void ldm_x4(uint32_t addr, uint32_t& r0, uint32_t& r1,
                                       uint32_t& r2, uint32_t& r3) {
    asm volatile("ldmatrix.sync.aligned.m8n8.x4.shared.b16 {%0,%1,%2,%3}, [%4];"
                 : "=r"(r0), "=r"(r1), "=r"(r2), "=r"(r3) : "r"(addr));
}

__device__ __forceinline__ void mma16816(float& c0, float& c1, float& c2, float& c3,
                                         uint32_t a0, uint32_t a1, uint32_t a2, uint32_t a3,
                                         uint32_t b0, uint32_t b1) {
    asm volatile("mma.sync.aligned.m16n8k16.row.col.f32.f16.f16.f32 "
                 "{%0,%1,%2,%3}, {%4,%5,%6,%7}, {%8,%9}, {%0,%1,%2,%3};"
                 : "+f"(c0), "+f"(c1), "+f"(c2), "+f"(c3)
                 : "r"(a0), "r"(a1), "r"(a2), "r"(a3), "r"(b0), "r"(b1));
}

// ---------------------------------------------------------------------------
// Kernel 1: decode every codebook entry once (65536 x 16)
// ---------------------------------------------------------------------------
__global__ void __launch_bounds__(256)
precompute_table(const float* __restrict__ codebook,
                 const float* __restrict__ W1, const float* __restrict__ b1,
                 const float* __restrict__ W2, const float* __restrict__ b2)
{
    __shared__ float sW1[D_LAT * HID];
    __shared__ float sW2[HID * BLOCK_];
    __shared__ float sb1[HID];
    __shared__ float sb2[BLOCK_];

    const int tid = threadIdx.x;
    for (int i = tid; i < D_LAT * HID; i += 256) sW1[i] = W1[i];
    for (int i = tid; i < HID * BLOCK_; i += 256) sW2[i] = W2[i];
    if (tid < HID)    sb1[tid] = b1[tid];
    if (tid < BLOCK_) sb2[tid] = b2[tid];
    __syncthreads();

    const int e = blockIdx.x * 256 + tid;

    float c[D_LAT];
    const float4* cb = reinterpret_cast<const float4*>(codebook + (size_t)e * D_LAT);
    {
        float4 v0 = cb[0], v1 = cb[1], v2 = cb[2], v3 = cb[3];
        c[0]=v0.x; c[1]=v0.y; c[2]=v0.z; c[3]=v0.w;
        c[4]=v1.x; c[5]=v1.y; c[6]=v1.z; c[7]=v1.w;
        c[8]=v2.x; c[9]=v2.y; c[10]=v2.z; c[11]=v2.w;
        c[12]=v3.x; c[13]=v3.y; c[14]=v3.z; c[15]=v3.w;
    }

    float h[HID];
    #pragma unroll
    for (int j = 0; j < HID; ++j) h[j] = sb1[j];
    #pragma unroll
    for (int d = 0; d < D_LAT; ++d) {
        const float cd = c[d];
        #pragma unroll
        for (int j = 0; j < HID; ++j) h[j] = fmaf(cd, sW1[d * HID + j], h[j]);
    }
    #pragma unroll
    for (int j = 0; j < HID; ++j) h[j] = fmaxf(h[j], 0.0f);

    float blk[BLOCK_];
    #pragma unroll
    for (int k = 0; k < BLOCK_; ++k) blk[k] = sb2[k];
    #pragma unroll
    for (int j = 0; j < HID; ++j) {
        const float hj = h[j];
        #pragma unroll
        for (int k = 0; k < BLOCK_; ++k) blk[k] = fmaf(hj, sW2[j * BLOCK_ + k], blk[k]);
    }

    float4* dst = reinterpret_cast<float4*>(g_table + (size_t)e * BLOCK_);
    dst[0] = make_float4(blk[0], blk[1], blk[2], blk[3]);
    dst[1] = make_float4(blk[4], blk[5], blk[6], blk[7]);
    dst[2] = make_float4(blk[8], blk[9], blk[10], blk[11]);
    dst[3] = make_float4(blk[12], blk[13], blk[14], blk[15]);
}

// ---------------------------------------------------------------------------
// Kernel 2 (fused): gather+destandardize W  AND  convert x -> fp16.
// Blocks [0, OUT_F): one block per W row.  Blocks [OUT_F, ...): x conversion.
// ---------------------------------------------------------------------------
#define XCONV_BLOCKS ((M_ROWS * K_DIM) / (256 * 8))   // 16384

__global__ void __launch_bounds__(256)
prep_kernel(const int* __restrict__ idx,
            const float* __restrict__ scale, const float* __restrict__ shift,
            const float* __restrict__ x)
{
    if (blockIdx.x < OUT_F) {
        __shared__ float s_s, s_sh;
        const int o = blockIdx.x;
        if (threadIdx.x == 0) { s_s = scale[o]; s_sh = shift[o]; }
        __syncthreads();

        const int b = o * 256 + threadIdx.x;
        const int e = idx[b];
        const float s  = s_s;
        const float sh = s_sh;

        const float4* src = reinterpret_cast<const float4*>(g_table + (size_t)e * BLOCK_);
        float4 v0 = src[0], v1 = src[1], v2 = src[2], v3 = src[3];
        float blk[16] = {v0.x,v0.y,v0.z,v0.w, v1.x,v1.y,v1.z,v1.w,
                         v2.x,v2.y,v2.z,v2.w, v3.x,v3.y,v3.z,v3.w};

        __align__(16) __half h16[16];
        #pragma unroll
        for (int q = 0; q < 16; ++q) h16[q] = __float2half_rn(fmaf(blk[q], s, sh));

        const size_t base = (size_t)o * IN_F + (size_t)threadIdx.x * 16;
        reinterpret_cast<uint4*>(g_Wh + base)[0] = reinterpret_cast<uint4*>(h16)[0];
        reinterpret_cast<uint4*>(g_Wh + base)[1] = reinterpret_cast<uint4*>(h16)[1];
    } else {
        const size_t t = (size_t)(blockIdx.x - OUT_F) * 256 + threadIdx.x;
        const size_t base = t * 8;
        float4 a = *reinterpret_cast<const float4*>(x + base);
        float4 b = *reinterpret_cast<const float4*>(x + base + 4);
        __align__(16) __half h[8];
        h[0]=__float2half_rn(a.x); h[1]=__float2half_rn(a.y);
        h[2]=__float2half_rn(a.z); h[3]=__float2half_rn(a.w);
        h[4]=__float2half_rn(b.x); h[5]=__float2half_rn(b.y);
        h[6]=__float2half_rn(b.z); h[7]=__float2half_rn(b.w);
        *reinterpret_cast<uint4*>(g_xh + base) = *reinterpret_cast<uint4*>(h);
    }
}

// ---------------------------------------------------------------------------
// Kernel 3: fp16 mma.sync GEMM, 4 warps of 64x64.
// R5 pipeline (wait_group 1 at top) + mid-iteration wait_group 1 that makes
// the cross-iteration kk0 fragment preload legal without shrinking the
// cp.async landing window.
// ---------------------------------------------------------------------------
#define STG_BYTES 32768
#define SMEM_TOTAL (STAGES * STG_BYTES)   // 96 KB; 2 CTAs/SM

__device__ __forceinline__ void load_stage(uint32_t sbase, int buf, int it,
                                           int bm0, int bn0, int tid)
{
    const uint32_t sA = sbase + buf * STG_BYTES;
    const uint32_t sB = sA + 16384;
    const size_t k0 = (size_t)it * BK;
    #pragma unroll
    for (int i = 0; i < 8; ++i) {
        const int c = tid + i * 128;          // 0..1023
        const int row = c >> 3;
        const int cx  = c & 7;
        const uint32_t soff = SWZ((uint32_t)(row * 128 + cx * 16));
        cp16(sA + soff, g_xh + (size_t)(bm0 + row) * K_DIM + k0 + cx * 8);
        cp16(sB + soff, g_Wh + (size_t)(bn0 + row) * K_DIM + k0 + cx * 8);
    }
}

__global__ void __launch_bounds__(THREADS, 2)
gemm_kernel(const float* __restrict__ bias, float* __restrict__ C)
{
    extern __shared__ char smem[];
    const uint32_t sbase = smem_u32(smem);
    const int tid  = threadIdx.x;
    const int lane = tid & 31;
    const int w    = tid >> 5;          // 0..3
    const int wm   = w >> 1;
    const int wn   = w & 1;
    const int bm0  = blockIdx.y * BM;
    const int bn0  = blockIdx.x * BN;

    float acc[4][8][4];
    #pragma unroll
    for (int mt = 0; mt < 4; ++mt)
        #pragma unroll
        for (int nt = 0; nt < 8; ++nt)
            #pragma unroll
            for (int q = 0; q < 4; ++q) acc[mt][nt][q] = 0.0f;

    // Prologue: fill buffers 0 and 1
    load_stage(sbase, 0, 0, bm0, bn0, tid);
    CP_COMMIT();
    load_stage(sbase, 1, 1, bm0, bn0, tid);
    CP_COMMIT();

    // Per-lane ldmatrix base offsets
    const int a_row = wm * 64 + (lane & 15);
    const int a_cb  = ((lane >> 4) & 1) * 16;
    const int b_row = wn * 64 + ((lane >> 4) & 1) * 8 + (lane & 7);
    const int b_cb  = ((lane >> 3) & 1) * 16;

    uint32_t a[2][4][4];
    uint32_t b[2][8][2];

    // Wait for stage 0 (group 1 may fly), preload kk=0 frags of stage 0.
    CP_WAIT1();
    __syncthreads();
    {
        const uint32_t sA = sbase;
        const uint32_t sB = sA + 16384;
        #pragma unroll
        for (int mt = 0; mt < 4; ++mt) {
            const uint32_t off = (uint32_t)((a_row + mt * 16) * 128 + a_cb);
            ldm_x4(sA + SWZ(off), a[0][mt][0], a[0][mt][1], a[0][mt][2], a[0][mt][3]);
        }
        #pragma unroll
        for (int ntp = 0; ntp < 4; ++ntp) {
            const uint32_t off = (uint32_t)((b_row + ntp * 16) * 128 + b_cb);
            uint32_t r0, r1, r2, r3;
            ldm_x4(sB + SWZ(off), r0, r1, r2, r3);
            b[0][ntp*2+0][0] = r0; b[0][ntp*2+0][1] = r1;
            b[0][ntp*2+1][0] = r2; b[0][ntp*2+1][1] = r3;
        }
    }

    for (int it = 0; it < NK; ++it) {
        // Stage `it` resident; stage `it+1` may still be in flight.
        CP_WAIT1();
        __syncthreads();   // buffer (it+2)%3 fully consumed in iter it-1 -> safe

        const int nxt = it + 2;
        if (nxt < NK) load_stage(sbase, nxt % STAGES, nxt, bm0, bn0, tid);
        CP_COMMIT();       // outstanding groups now: {it+1, it+2}

        const uint32_t sA = sbase + (it % STAGES) * STG_BYTES;
        const uint32_t sB = sA + 16384;
        const uint32_t sAn = sbase + ((it + 1) % STAGES) * STG_BYTES;
        const uint32_t sBn = sAn + 16384;
        const bool have_next = (it + 1) < NK;

        // kk = 0..2: prefetch kk+1 frags from current stage, MMA kk
        #pragma unroll
        for (int kk = 0; kk < 3; ++kk) {
            const int cur = kk & 1;
            const int nxb = cur ^ 1;
            const int kc = (kk + 1) * 32;
            #pragma unroll
            for (int mt = 0; mt < 4; ++mt) {
                const uint32_t off = (uint32_t)((a_row + mt * 16) * 128 + kc + a_cb);
                ldm_x4(sA + SWZ(off), a[nxb][mt][0], a[nxb][mt][1], a[nxb][mt][2], a[nxb][mt][3]);
            }
            #pragma unroll
            for (int ntp = 0; ntp < 4; ++ntp) {
                const uint32_t off = (uint32_t)((b_row + ntp * 16) * 128 + kc + b_cb);
                uint32_t r0, r1, r2, r3;
                ldm_x4(sB + SWZ(off), r0, r1, r2, r3);
                b[nxb][ntp*2+0][0] = r0; b[nxb][ntp*2+0][1] = r1;
                b[nxb][ntp*2+1][0] = r2; b[nxb][ntp*2+1][1] = r3;
            }
            #pragma unroll
            for (int mt = 0; mt < 4; ++mt)
                #pragma unroll
                for (int nt = 0; nt < 8; ++nt)
                    mma16816(acc[mt][nt][0], acc[mt][nt][1], acc[mt][nt][2], acc[mt][nt][3],
                             a[cur][mt][0], a[cur][mt][1], a[cur][mt][2], a[cur][mt][3],
                             b[cur][nt][0], b[cur][nt][1]);
        }

        // Mid-iteration wait: outstanding {it+1, it+2} -> wait_group 1 proves
        // stage it+1 is resident. Makes the next-stage frag preload legal.
        CP_WAIT1();

        // kk = 3: preload NEXT stage's kk=0 frags, MMA kk=3
        {
            const int cur = 1;   // kk=3 parity
            const int nxb = 0;
            if (have_next) {
                #pragma unroll
                for (int mt = 0; mt < 4; ++mt) {
                    const uint32_t off = (uint32_t)((a_row + mt * 16) * 128 + a_cb);
                    ldm_x4(sAn + SWZ(off), a[nxb][mt][0], a[nxb][mt][1], a[nxb][mt][2], a[nxb][mt][3]);
                }
                #pragma unroll
                for (int ntp = 0; ntp < 4; ++ntp) {
                    const uint32_t off = (uint32_t)((b_row + ntp * 16) * 128 + b_cb);
                    uint32_t r0, r1, r2, r3;
                    ldm_x4(sBn + SWZ(off), r0, r1, r2, r3);
                    b[nxb][ntp*2+0][0] = r0; b[nxb][ntp*2+0][1] = r1;
                    b[nxb][ntp*2+1][0] = r2; b[nxb][ntp*2+1][1] = r3;
                }
            }
            #pragma unroll
            for (int mt = 0; mt < 4; ++mt)
                #pragma unroll
                for (int nt = 0; nt < 8; ++nt)
                    mma16816(acc[mt][nt][0], acc[mt][nt][1], acc[mt][nt][2], acc[mt][nt][3],
                             a[cur][mt][0], a[cur][mt][1], a[cur][mt][2], a[cur][mt][3],
                             b[cur][nt][0], b[cur][nt][1]);
        }
    }

    // Epilogue
    #pragma unroll
    for (int nt = 0; nt < 8; ++nt) {
        const int col = bn0 + wn * 64 + nt * 8 + (lane & 3) * 2;
        const float bx = __ldg(bias + col);
        const float by = __ldg(bias + col + 1);
        #pragma unroll
        for (int mt = 0; mt < 4; ++mt) {
            const int r0 = bm0 + wm * 64 + mt * 16 + (lane >> 2);
            float2 v0 = make_float2(acc[mt][nt][0] + bx, acc[mt][nt][1] + by);
            float2 v1 = make_float2(acc[mt][nt][2] + bx, acc[mt][nt][3] + by);
            *reinterpret_cast<float2*>(C + (size_t)r0 * N_DIM + col) = v0;
            *reinterpret_cast<float2*>(C + (size_t)(r0 + 8) * N_DIM + col) = v1;
        }
    }
}

// ---------------------------------------------------------------------------
// kernel_launch
// ---------------------------------------------------------------------------
extern "C" void kernel_launch(void* const* d_in, const int* in_sizes, int n_in,
                              void* d_out, int out_size)
{
    const float* x        = (const float*)d_in[0];
    const int*   y_in_idx = (const int*)  d_in[1];
    const float* codebook = (const float*)d_in[2];
    const float* W1       = (const float*)d_in[3];
    const float* b1       = (const float*)d_in[4];
    const float* W2       = (const float*)d_in[5];
    const float* b2       = (const float*)d_in[6];
    const float* scale    = (const float*)d_in[7];
    const float* shift    = (const float*)d_in[8];
    const float* bias     = (const float*)d_in[9];
    float* out = (float*)d_out;

    cudaFuncSetAttribute(gemm_kernel, cudaFuncAttributeMaxDynamicSharedMemorySize, SMEM_TOTAL);

    precompute_table<<<KSIZE / 256, 256>>>(codebook, W1, b1, W2, b2);
    prep_kernel<<<OUT_F + XCONV_BLOCKS, 256>>>(y_in_idx, scale, shift, x);

    dim3 grid(N_DIM / BN, M_ROWS / BM);
    gemm_kernel<<<grid, THREADS, SMEM_TOTAL>>>(bias, out);
}

// round 8
// speedup vs baseline: 1.0235x; 1.0135x over previous
#include <cuda_runtime.h>
#include <cuda_fp16.h>
#include <cstdint>

// ---------------------------------------------------------------------------
// Problem constants
// ---------------------------------------------------------------------------
#define IN_F   4096
#define OUT_F  4096
#define BLOCK_ 16
#define D_LAT  16
#define HID    64
#define KSIZE  65536
#define NB     (IN_F * OUT_F / BLOCK_)
#define M_ROWS 8192
#define K_DIM  4096
#define N_DIM  4096

// GEMM tiling: CTA 128x128, 4 warps of 64x64, BK=64, 3 stages  (R5 config)
#define BM 128
#define BN 128
#define BK 64
#define STAGES 3
#define NK (K_DIM / BK)   // 64
#define THREADS 128

// ---------------------------------------------------------------------------
// Scratch
// ---------------------------------------------------------------------------
__device__ float  g_table[(size_t)KSIZE * BLOCK_];
__device__ __half g_Wh[(size_t)OUT_F * IN_F];
__device__ __half g_xh[(size_t)M_ROWS * IN_F];

// ---------------------------------------------------------------------------
// Helpers
// ---------------------------------------------------------------------------
__device__ __forceinline__ uint32_t smem_u32(const void* p) {
    return (uint32_t)__cvta_generic_to_shared(p);
}
#define SWZ(o) ((o) ^ (((o) >> 3) & 0x70))

__device__ __forceinline__ void cp16(uint32_t saddr, const void* gaddr) {
    asm volatile("cp.async.cg.shared.global [%0], [%1], 16;" :: "r"(saddr), "l"(gaddr));
}
#define CP_COMMIT() asm volatile("cp.async.commit_group;" ::: "memory")
#define CP_WAIT1()  asm volatile("cp.async.wait_group 1;" ::: "memory")

__device__ __forceinline__ void ldm_x4(uint32_t addr, uint32_t& r0, uint32_t& r1,
                                       uint32_t& r2, uint32_t& r3) {
    asm volatile("ldmatrix.sync.aligned.m8n8.x4.shared.b16 {%0,%1,%2,%3}, [%4];"
                 : "=r"(r0), "=r"(r1), "=r"(r2), "=r"(r3) : "r"(addr));
}

__device__ __forceinline__ void mma16816(float& c0, float& c1, float& c2, float& c3,
                                         uint32_t a0, uint32_t a1, uint32_t a2, uint32_t a3,
                                         uint32_t b0, uint32_t b1) {
    asm volatile("mma.sync.aligned.m16n8k16.row.col.f32.f16.f16.f32 "
                 "{%0,%1,%2,%3}, {%4,%5,%6,%7}, {%8,%9}, {%0,%1,%2,%3};"
                 : "+f"(c0), "+f"(c1), "+f"(c2), "+f"(c3)
                 : "r"(a0), "r"(a1), "r"(a2), "r"(a3), "r"(b0), "r"(b1));
}

// ---------------------------------------------------------------------------
// Kernel 1: decode every codebook entry once (65536 x 16).
// 512 CTAs x 128 threads for better wave balance (148 SMs).
// ---------------------------------------------------------------------------
__global__ void __launch_bounds__(128)
precompute_table(const float* __restrict__ codebook,
                 const float* __restrict__ W1, const float* __restrict__ b1,
                 const float* __restrict__ W2, const float* __restrict__ b2)
{
    __shared__ float sW1[D_LAT * HID];
    __shared__ float sW2[HID * BLOCK_];
    __shared__ float sb1[HID];
    __shared__ float sb2[BLOCK_];

    const int tid = threadIdx.x;
    for (int i = tid; i < D_LAT * HID; i += 128) sW1[i] = W1[i];
    for (int i = tid; i < HID * BLOCK_; i += 128) sW2[i] = W2[i];
    if (tid < HID)    sb1[tid] = b1[tid];
    if (tid < BLOCK_) sb2[tid] = b2[tid];
    __syncthreads();

    const int e = blockIdx.x * 128 + tid;

    float c[D_LAT];
    const float4* cb = reinterpret_cast<const float4*>(codebook + (size_t)e * D_LAT);
    {
        float4 v0 = cb[0], v1 = cb[1], v2 = cb[2], v3 = cb[3];
        c[0]=v0.x; c[1]=v0.y; c[2]=v0.z; c[3]=v0.w;
        c[4]=v1.x; c[5]=v1.y; c[6]=v1.z; c[7]=v1.w;
        c[8]=v2.x; c[9]=v2.y; c[10]=v2.z; c[11]=v2.w;
        c[12]=v3.x; c[13]=v3.y; c[14]=v3.z; c[15]=v3.w;
    }

    float h[HID];
    #pragma unroll
    for (int j = 0; j < HID; ++j) h[j] = sb1[j];
    #pragma unroll
    for (int d = 0; d < D_LAT; ++d) {
        const float cd = c[d];
        #pragma unroll
        for (int j = 0; j < HID; ++j) h[j] = fmaf(cd, sW1[d * HID + j], h[j]);
    }
    #pragma unroll
    for (int j = 0; j < HID; ++j) h[j] = fmaxf(h[j], 0.0f);

    float blk[BLOCK_];
    #pragma unroll
    for (int k = 0; k < BLOCK_; ++k) blk[k] = sb2[k];
    #pragma unroll
    for (int j = 0; j < HID; ++j) {
        const float hj = h[j];
        #pragma unroll
        for (int k = 0; k < BLOCK_; ++k) blk[k] = fmaf(hj, sW2[j * BLOCK_ + k], blk[k]);
    }

    float4* dst = reinterpret_cast<float4*>(g_table + (size_t)e * BLOCK_);
    dst[0] = make_float4(blk[0], blk[1], blk[2], blk[3]);
    dst[1] = make_float4(blk[4], blk[5], blk[6], blk[7]);
    dst[2] = make_float4(blk[8], blk[9], blk[10], blk[11]);
    dst[3] = make_float4(blk[12], blk[13], blk[14], blk[15]);
}

// ---------------------------------------------------------------------------
// Kernel 2 (fused): gather+destandardize W  AND  convert x -> fp16.
// ---------------------------------------------------------------------------
#define XCONV_BLOCKS ((M_ROWS * K_DIM) / (256 * 8))   // 16384

__global__ void __launch_bounds__(256)
prep_kernel(const int* __restrict__ idx,
            const float* __restrict__ scale, const float* __restrict__ shift,
            const float* __restrict__ x)
{
    if (blockIdx.x < OUT_F) {
        __shared__ float s_s, s_sh;
        const int o = blockIdx.x;
        if (threadIdx.x == 0) { s_s = scale[o]; s_sh = shift[o]; }
        __syncthreads();

        const int b = o * 256 + threadIdx.x;
        const int e = idx[b];
        const float s  = s_s;
        const float sh = s_sh;

        const float4* src = reinterpret_cast<const float4*>(g_table + (size_t)e * BLOCK_);
        float4 v0 = src[0], v1 = src[1], v2 = src[2], v3 = src[3];
        float blk[16] = {v0.x,v0.y,v0.z,v0.w, v1.x,v1.y,v1.z,v1.w,
                         v2.x,v2.y,v2.z,v2.w, v3.x,v3.y,v3.z,v3.w};

        __align__(16) __half h16[16];
        #pragma unroll
        for (int q = 0; q < 16; ++q) h16[q] = __float2half_rn(fmaf(blk[q], s, sh));

        const size_t base = (size_t)o * IN_F + (size_t)threadIdx.x * 16;
        reinterpret_cast<uint4*>(g_Wh + base)[0] = reinterpret_cast<uint4*>(h16)[0];
        reinterpret_cast<uint4*>(g_Wh + base)[1] = reinterpret_cast<uint4*>(h16)[1];
    } else {
        const size_t t = (size_t)(blockIdx.x - OUT_F) * 256 + threadIdx.x;
        const size_t base = t * 8;
        float4 a = *reinterpret_cast<const float4*>(x + base);
        float4 b = *reinterpret_cast<const float4*>(x + base + 4);
        __align__(16) __half h[8];
        h[0]=__float2half_rn(a.x); h[1]=__float2half_rn(a.y);
        h[2]=__float2half_rn(a.z); h[3]=__float2half_rn(a.w);
        h[4]=__float2half_rn(b.x); h[5]=__float2half_rn(b.y);
        h[6]=__float2half_rn(b.z); h[7]=__float2half_rn(b.w);
        *reinterpret_cast<uint4*>(g_xh + base) = *reinterpret_cast<uint4*>(h);
    }
}

// ---------------------------------------------------------------------------
// Kernel 3: fp16 mma.sync GEMM — EXACT R5 schedule (measured 575us).
// 4 warps of 64x64, reg-double-buffered fragments, wait_group 1 at top.
// ---------------------------------------------------------------------------
#define STG_BYTES 32768
#define SMEM_TOTAL (STAGES * STG_BYTES)   // 96 KB; 2 CTAs/SM

__device__ __forceinline__ void load_stage(uint32_t sbase, int buf, int it,
                                           int bm0, int bn0, int tid)
{
    const uint32_t sA = sbase + buf * STG_BYTES;
    const uint32_t sB = sA + 16384;
    const size_t k0 = (size_t)it * BK;
    #pragma unroll
    for (int i = 0; i < 8; ++i) {
        const int c = tid + i * 128;          // 0..1023
        const int row = c >> 3;
        const int cx  = c & 7;
        const uint32_t soff = SWZ((uint32_t)(row * 128 + cx * 16));
        cp16(sA + soff, g_xh + (size_t)(bm0 + row) * K_DIM + k0 + cx * 8);
        cp16(sB + soff, g_Wh + (size_t)(bn0 + row) * K_DIM + k0 + cx * 8);
    }
}

__global__ void __launch_bounds__(THREADS, 2)
gemm_kernel(const float* __restrict__ bias, float* __restrict__ C)
{
    extern __shared__ char smem[];
    const uint32_t sbase = smem_u32(smem);
    const int tid  = threadIdx.x;
    const int lane = tid & 31;
    const int w    = tid >> 5;          // 0..3
    const int wm   = w >> 1;            // m offset wm*64
    const int wn   = w & 1;             // n offset wn*64
    const int bm0  = blockIdx.y * BM;
    const int bn0  = blockIdx.x * BN;

    float acc[4][8][4];
    #pragma unroll
    for (int mt = 0; mt < 4; ++mt)
        #pragma unroll
        for (int nt = 0; nt < 8; ++nt)
            #pragma unroll
            for (int q = 0; q < 4; ++q) acc[mt][nt][q] = 0.0f;

    // Prologue: fill 2 of 3 buffers
    load_stage(sbase, 0, 0, bm0, bn0, tid);
    CP_COMMIT();
    load_stage(sbase, 1, 1, bm0, bn0, tid);
    CP_COMMIT();

    // Per-lane ldmatrix base offsets
    const int a_row = wm * 64 + (lane & 15);
    const int a_cb  = ((lane >> 4) & 1) * 16;
    const int b_row = wn * 64 + ((lane >> 4) & 1) * 8 + (lane & 7);
    const int b_cb  = ((lane >> 3) & 1) * 16;

    for (int it = 0; it < NK; ++it) {
        CP_WAIT1();
        __syncthreads();

        const int buf = it % STAGES;
        const uint32_t sA = sbase + buf * STG_BYTES;
        const uint32_t sB = sA + 16384;

        // Double-buffered fragments across kk steps
        uint32_t a[2][4][4];
        uint32_t b[2][8][2];

        // Load kk=0 fragments
        #pragma unroll
        for (int mt = 0; mt < 4; ++mt) {
            const uint32_t off = (uint32_t)((a_row + mt * 16) * 128 + a_cb);
            ldm_x4(sA + SWZ(off), a[0][mt][0], a[0][mt][1], a[0][mt][2], a[0][mt][3]);
        }
        #pragma unroll
        for (int ntp = 0; ntp < 4; ++ntp) {
            const uint32_t off = (uint32_t)((b_row + ntp * 16) * 128 + b_cb);
            uint32_t r0, r1, r2, r3;
            ldm_x4(sB + SWZ(off), r0, r1, r2, r3);
            b[0][ntp*2+0][0] = r0; b[0][ntp*2+0][1] = r1;
            b[0][ntp*2+1][0] = r2; b[0][ntp*2+1][1] = r3;
        }

        // Issue next stage's cp.async early (overlaps with MMAs below)
        const int nxt = it + 2;
        if (nxt < NK) load_stage(sbase, nxt % STAGES, nxt, bm0, bn0, tid);
        CP_COMMIT();

        #pragma unroll
        for (int kk = 0; kk < 4; ++kk) {
            const int cur = kk & 1;
            const int nxb = cur ^ 1;
            if (kk < 3) {
                const int kc = (kk + 1) * 32;
                #pragma unroll
                for (int mt = 0; mt < 4; ++mt) {
                    const uint32_t off = (uint32_t)((a_row + mt * 16) * 128 + kc + a_cb);
                    ldm_x4(sA + SWZ(off), a[nxb][mt][0], a[nxb][mt][1], a[nxb][mt][2], a[nxb][mt][3]);
                }
                #pragma unroll
                for (int ntp = 0; ntp < 4; ++ntp) {
                    const uint32_t off = (uint32_t)((b_row + ntp * 16) * 128 + kc + b_cb);
                    uint32_t r0, r1, r2, r3;
                    ldm_x4(sB + SWZ(off), r0, r1, r2, r3);
                    b[nxb][ntp*2+0][0] = r0; b[nxb][ntp*2+0][1] = r1;
                    b[nxb][ntp*2+1][0] = r2; b[nxb][ntp*2+1][1] = r3;
                }
            }
            #pragma unroll
            for (int mt = 0; mt < 4; ++mt)
                #pragma unroll
                for (int nt = 0; nt < 8; ++nt)
                    mma16816(acc[mt][nt][0], acc[mt][nt][1], acc[mt][nt][2], acc[mt][nt][3],
                             a[cur][mt][0], a[cur][mt][1], a[cur][mt][2], a[cur][mt][3],
                             b[cur][nt][0], b[cur][nt][1]);
        }
        __syncthreads();
    }

    // Epilogue
    #pragma unroll
    for (int nt = 0; nt < 8; ++nt) {
        const int col = bn0 + wn * 64 + nt * 8 + (lane & 3) * 2;
        const float bx = __ldg(bias + col);
        const float by = __ldg(bias + col + 1);
        #pragma unroll
        for (int mt = 0; mt < 4; ++mt) {
            const int r0 = bm0 + wm * 64 + mt * 16 + (lane >> 2);
            float2 v0 = make_float2(acc[mt][nt][0] + bx, acc[mt][nt][1] + by);
            float2 v1 = make_float2(acc[mt][nt][2] + bx, acc[mt][nt][3] + by);
            *reinterpret_cast<float2*>(C + (size_t)r0 * N_DIM + col) = v0;
            *reinterpret_cast<float2*>(C + (size_t)(r0 + 8) * N_DIM + col) = v1;
        }
    }
}

// ---------------------------------------------------------------------------
// kernel_launch
// ---------------------------------------------------------------------------
extern "C" void kernel_launch(void* const* d_in, const int* in_sizes, int n_in,
                              void* d_out, int out_size)
{
    const float* x        = (const float*)d_in[0];
    const int*   y_in_idx = (const int*)  d_in[1];
    const float* codebook = (const float*)d_in[2];
    const float* W1       = (const float*)d_in[3];
    const float* b1       = (const float*)d_in[4];
    const float* W2       = (const float*)d_in[5];
    const float* b2       = (const float*)d_in[6];
    const float* scale    = (const float*)d_in[7];
    const float* shift    = (const float*)d_in[8];
    const float* bias     = (const float*)d_in[9];
    float* out = (float*)d_out;

    cudaFuncSetAttribute(gemm_kernel, cudaFuncAttributeMaxDynamicSharedMemorySize, SMEM_TOTAL);

    precompute_table<<<KSIZE / 128, 128>>>(codebook, W1, b1, W2, b2);
    prep_kernel<<<OUT_F + XCONV_BLOCKS, 256>>>(y_in_idx, scale, shift, x);

    dim3 grid(N_DIM / BN, M_ROWS / BM);
    gemm_kernel<<<grid, THREADS, SMEM_TOTAL>>>(bias, out);
}